// round 1
// baseline (speedup 1.0000x reference)
#include <cuda_runtime.h>
#include <cuda_bf16.h>
#include <math.h>

// Problem constants
#define BB 8
#define MM 256
#define EE 128
#define KK 16
#define HH 1024
#define AA 256
#define RR 1024
#define RMS 512
#define BE (BB*EE)          // 1024
#define BEK (BB*EE*KK)      // 16384
#define ZW (HH + RMS)       // 1536

// Scratch (device globals; allocation is forbidden)
__device__ float g_Cv[BEK * AA];       // 16 MB
__device__ float g_Cu[BEK * AA];       // 16 MB
__device__ float g_attn[BEK];
__device__ float g_Z[BE * ZW];         // concat(entity_reprs, s2)
__device__ float g_sw[RR * HH];
__device__ float g_s[BE * RR];
__device__ float g_RMt[RMS * RR];

// ---------------------------------------------------------------------------
// Tiled fp32 NT GEMM: C[M,N] = A[M,K] * B[N,K]^T (+ bias[n])
// A optionally gathered: row gm -> mention_reprs[(gm>>11)*256 + gidx[gm]]
// BM=128 BN=64 BK=16, 256 threads, 8x4 per-thread tile.
// ---------------------------------------------------------------------------
#define BM 128
#define BN 64
#define BK 16
#define BMP (BM + 4)
#define BNP (BN + 4)

template<bool GATHER, bool BIAS>
__global__ void __launch_bounds__(256)
sgemm_nt(const float* __restrict__ A, const float* __restrict__ B,
         const float* __restrict__ bias, float* __restrict__ C,
         int Mdim, int Ndim, int Kdim, int lda, int ldc,
         const int* __restrict__ gidx, const float* __restrict__ gbase)
{
    __shared__ float As[BK][BMP];
    __shared__ float Bs[BK][BNP];

    const int tid = threadIdx.x;
    const int bx = blockIdx.x;   // N tiles
    const int by = blockIdx.y;   // M tiles

    // --- staging thread mapping ---
    const int ar  = tid >> 2;          // 0..63
    const int ac4 = (tid & 3) << 2;    // 0,4,8,12

    const float* aptr0;
    const float* aptr1;
    {
        int gm0 = by * BM + ar;
        int gm1 = gm0 + 64;
        if (GATHER) {
            int b0 = gm0 >> 11;            // /(E*K)=2048
            int b1 = gm1 >> 11;
            aptr0 = gbase + (size_t)(b0 * MM + gidx[gm0]) * HH + ac4;
            aptr1 = gbase + (size_t)(b1 * MM + gidx[gm1]) * HH + ac4;
        } else {
            aptr0 = A + (size_t)gm0 * lda + ac4;
            aptr1 = A + (size_t)gm1 * lda + ac4;
        }
    }
    const float* bptr = B + (size_t)(bx * BN + ar) * Kdim + ac4;

    const int tx = tid & 15;   // N dir
    const int ty = tid >> 4;   // M dir

    float acc[8][4];
#pragma unroll
    for (int i = 0; i < 8; i++)
#pragma unroll
        for (int j = 0; j < 4; j++) acc[i][j] = 0.f;

    const int nK = Kdim / BK;
    for (int t = 0; t < nK; t++) {
        const int k0 = t * BK;
        // stage A (two rows per thread)
        float4 a0 = *(const float4*)(aptr0 + k0);
        float4 a1 = *(const float4*)(aptr1 + k0);
        float4 b0 = *(const float4*)(bptr  + k0);
        As[ac4 + 0][ar]      = a0.x;
        As[ac4 + 1][ar]      = a0.y;
        As[ac4 + 2][ar]      = a0.z;
        As[ac4 + 3][ar]      = a0.w;
        As[ac4 + 0][ar + 64] = a1.x;
        As[ac4 + 1][ar + 64] = a1.y;
        As[ac4 + 2][ar + 64] = a1.z;
        As[ac4 + 3][ar + 64] = a1.w;
        Bs[ac4 + 0][ar] = b0.x;
        Bs[ac4 + 1][ar] = b0.y;
        Bs[ac4 + 2][ar] = b0.z;
        Bs[ac4 + 3][ar] = b0.w;
        __syncthreads();

#pragma unroll
        for (int kk = 0; kk < BK; kk++) {
            float4 af0 = *(const float4*)&As[kk][ty * 8];
            float4 af1 = *(const float4*)&As[kk][ty * 8 + 4];
            float4 bf  = *(const float4*)&Bs[kk][tx * 4];
            float a[8] = {af0.x, af0.y, af0.z, af0.w, af1.x, af1.y, af1.z, af1.w};
            float b[4] = {bf.x, bf.y, bf.z, bf.w};
#pragma unroll
            for (int i = 0; i < 8; i++)
#pragma unroll
                for (int j = 0; j < 4; j++)
                    acc[i][j] = fmaf(a[i], b[j], acc[i][j]);
        }
        __syncthreads();
    }

    // epilogue
    const int cm = by * BM + ty * 8;
    const int cn = bx * BN + tx * 4;
    float4 bv4 = make_float4(0.f, 0.f, 0.f, 0.f);
    if (BIAS) bv4 = *(const float4*)(bias + cn);
#pragma unroll
    for (int i = 0; i < 8; i++) {
        float4 v;
        v.x = acc[i][0] + bv4.x;
        v.y = acc[i][1] + bv4.y;
        v.z = acc[i][2] + bv4.z;
        v.w = acc[i][3] + bv4.w;
        *(float4*)&C[(size_t)(cm + i) * ldc + cn] = v;
    }
}

// ---------------------------------------------------------------------------
// logits + masked softmax over K, fused. 1 block per (b,e), 16 warps (1/k).
// ---------------------------------------------------------------------------
__global__ void __launch_bounds__(512)
logits_softmax(const float* __restrict__ Cv, const float* __restrict__ Cu,
               const float* __restrict__ bv, const float* __restrict__ bu,
               const float* __restrict__ Wa, const float* __restrict__ ba,
               const int* __restrict__ mask, float* __restrict__ attn)
{
    const int be = blockIdx.x;
    const int warp = threadIdx.x >> 5;   // k
    const int lane = threadIdx.x & 31;
    const int row = be * KK + warp;

    float sum = 0.f;
#pragma unroll
    for (int a = lane; a < AA; a += 32) {
        float v = tanhf(Cv[(size_t)row * AA + a] + bv[a]);
        float u = 1.f / (1.f + expf(-(Cu[(size_t)row * AA + a] + bu[a])));
        sum += v * u * Wa[a];
    }
#pragma unroll
    for (int o = 16; o; o >>= 1) sum += __shfl_xor_sync(0xffffffffu, sum, o);

    __shared__ float sl[KK];
    if (lane == 0) {
        float l = sum + ba[0];
        if (mask[row] == 0) l = -1e25f;
        sl[warp] = l;
    }
    __syncthreads();
    if (threadIdx.x == 0) {
        float mx = sl[0];
#pragma unroll
        for (int k = 1; k < KK; k++) mx = fmaxf(mx, sl[k]);
        float e[KK];
        float s = 0.f;
#pragma unroll
        for (int k = 0; k < KK; k++) { e[k] = expf(sl[k] - mx); s += e[k]; }
        float inv = 1.f / s;
#pragma unroll
        for (int k = 0; k < KK; k++) attn[be * KK + k] = e[k] * inv;
    }
}

// ---------------------------------------------------------------------------
// Weighted pooling over K mentions -> entity_reprs into Z[:, 0:H]
// ---------------------------------------------------------------------------
__global__ void __launch_bounds__(256)
pool_kernel(const float* __restrict__ attn, const int* __restrict__ ent,
            const float* __restrict__ mr, float* __restrict__ Z)
{
    const int be = blockIdx.x;
    const int b = be >> 7;   // /E
    __shared__ float w[KK];
    __shared__ int rows[KK];
    if (threadIdx.x < KK) {
        w[threadIdx.x] = attn[be * KK + threadIdx.x];
        rows[threadIdx.x] = b * MM + ent[be * KK + threadIdx.x];
    }
    __syncthreads();
    for (int h = threadIdx.x; h < HH; h += 256) {
        float s = 0.f;
#pragma unroll
        for (int k = 0; k < KK; k++)
            s = fmaf(w[k], mr[(size_t)rows[k] * HH + h], s);
        Z[(size_t)be * ZW + h] = s;
    }
}

// ---------------------------------------------------------------------------
// Transpose relation_memory [R, RMS] -> RMt [RMS, R]
// ---------------------------------------------------------------------------
__global__ void __launch_bounds__(1024)
transpose_rm(const float* __restrict__ RM, float* __restrict__ RMt)
{
    __shared__ float t[32][33];
    const int r0 = blockIdx.y * 32;
    const int m0 = blockIdx.x * 32;
    t[threadIdx.y][threadIdx.x] = RM[(size_t)(r0 + threadIdx.y) * RMS + m0 + threadIdx.x];
    __syncthreads();
    RMt[(size_t)(m0 + threadIdx.y) * RR + r0 + threadIdx.x] = t[threadIdx.x][threadIdx.y];
}

// ---------------------------------------------------------------------------
extern "C" void kernel_launch(void* const* d_in, const int* in_sizes, int n_in,
                              void* d_out, int out_size)
{
    const float* mr   = (const float*)d_in[0];
    const int*   ent  = (const int*)  d_in[1];
    const int*   emask= (const int*)  d_in[2];
    const float* RM   = (const float*)d_in[3];
    const float* Wv   = (const float*)d_in[4];
    const float* bv   = (const float*)d_in[5];
    const float* Wu   = (const float*)d_in[6];
    const float* bu   = (const float*)d_in[7];
    const float* Wa   = (const float*)d_in[8];
    const float* ba   = (const float*)d_in[9];
    const float* Wr   = (const float*)d_in[10];
    const float* br   = (const float*)d_in[11];
    const float* Wo   = (const float*)d_in[12];
    const float* bo   = (const float*)d_in[13];
    float* out = (float*)d_out;

    float *Cv, *Cu, *attn, *Z, *sw, *s, *RMt;
    cudaGetSymbolAddress((void**)&Cv,  g_Cv);
    cudaGetSymbolAddress((void**)&Cu,  g_Cu);
    cudaGetSymbolAddress((void**)&attn,g_attn);
    cudaGetSymbolAddress((void**)&Z,   g_Z);
    cudaGetSymbolAddress((void**)&sw,  g_sw);
    cudaGetSymbolAddress((void**)&s,   g_s);
    cudaGetSymbolAddress((void**)&RMt, g_RMt);

    // Stage 1: gathered cluster GEMMs (the 17-GFLOP pair)
    {
        dim3 grid(AA / BN, BEK / BM);   // (4, 128)
        sgemm_nt<true, false><<<grid, 256>>>(nullptr, Wv, nullptr, Cv,
                                             BEK, AA, HH, HH, AA, ent, mr);
        sgemm_nt<true, false><<<grid, 256>>>(nullptr, Wu, nullptr, Cu,
                                             BEK, AA, HH, HH, AA, ent, mr);
    }

    // Independent prep (can overlap in graph): RM transpose, s_w GEMM
    transpose_rm<<<dim3(RMS / 32, RR / 32), dim3(32, 32)>>>(RM, RMt);
    sgemm_nt<false, true><<<dim3(HH / BN, RR / BM), 256>>>(
        RM, Wr, br, sw, RR, HH, RMS, RMS, HH, nullptr, nullptr);

    // Stage 2: logits + softmax, pooling
    logits_softmax<<<BE, 512>>>(Cv, Cu, bv, bu, Wa, ba, emask, attn);
    pool_kernel<<<BE, 256>>>(attn, ent, mr, Z);

    // Stage 3: s = E · s_w^T   [1024,1024,1024]
    sgemm_nt<false, false><<<dim3(RR / BN, BE / BM), 256>>>(
        Z, sw, nullptr, s, BE, RR, HH, ZW, RR, nullptr, nullptr);

    // Stage 4: s2 = s · RM  (via RMt NT)  -> Z[:, H:H+RMS]
    sgemm_nt<false, false><<<dim3(RMS / BN, BE / BM), 256>>>(
        s, RMt, nullptr, Z + HH, BE, RMS, RR, RR, ZW, nullptr, nullptr);

    // Stage 5: out = Z · Wo^T + bo   [1024,1024,1536]
    sgemm_nt<false, true><<<dim3(HH / BN, BE / BM), 256>>>(
        Z, Wo, bo, out, BE, HH, ZW, ZW, HH, nullptr, nullptr);

    (void)in_sizes; (void)n_in; (void)out_size;
}

// round 2
// speedup vs baseline: 2.8276x; 2.8276x over previous
#include <cuda_runtime.h>
#include <cuda_bf16.h>
#include <math.h>

// Problem constants
#define BB 8
#define MM 256
#define EE 128
#define KK 16
#define HH 1024
#define AA 256
#define RR 1024
#define RMS 512
#define BE (BB*EE)          // 1024
#define BM_TOT (BB*MM)      // 2048 unique mentions
#define ZW (HH + RMS)       // 1536

// Scratch (device globals; allocation is forbidden)
__device__ float g_W[2 * AA * HH];      // concat(Wv, Wu)  [512,1024]
__device__ float g_P[BM_TOT * 2 * AA];  // P = MR @ g_W^T  [2048,512]
__device__ float g_L[BM_TOT];           // per-mention logits
__device__ float g_attn[BE * KK];
__device__ float g_E[BE * HH];          // entity reprs
__device__ float g_swT[HH * RR];        // (RM @ Wr^T + br)^T  [1024,1024]
__device__ float g_RMt[RMS * RR];       // RM^T [512,1024]
__device__ float g_T[HH * RMS];         // swT @ RM  [1024,512]
__device__ float g_G[HH * HH];          // Wo1 + Wo2 @ T^T (transposed eff. weight)

// ---------------------------------------------------------------------------
// Double-buffered fp32 NT GEMM: C[M,N] = A[M,K] * B[N,K]^T (+ epilogue)
// BM=BN=64, BK=16, 128 threads, 8x4 per-thread tile.
// MODE: 0=none, 1=col bias (bias[n]), 2=add C matrix, 3=row bias (bias[m])
// ---------------------------------------------------------------------------
#define BM 64
#define BN 64
#define BK 16

template<int MODE>
__global__ void __launch_bounds__(128)
sgemm_nt(const float* __restrict__ A, const float* __restrict__ B,
         const float* __restrict__ bias, const float* __restrict__ Cadd,
         float* __restrict__ C, int lda, int ldb, int ldc, int ldadd, int Kdim)
{
    __shared__ float As[2][BK][BM + 4];
    __shared__ float Bs[2][BK][BN + 4];

    const int tid = threadIdx.x;
    const int bx = blockIdx.x;   // N tiles
    const int by = blockIdx.y;   // M tiles

    const int r0  = tid >> 2;          // 0..31
    const int c4  = (tid & 3) << 2;    // 0,4,8,12

    const float* aptr0 = A + (size_t)(by * BM + r0)      * lda + c4;
    const float* aptr1 = A + (size_t)(by * BM + r0 + 32) * lda + c4;
    const float* bptr0 = B + (size_t)(bx * BN + r0)      * ldb + c4;
    const float* bptr1 = B + (size_t)(bx * BN + r0 + 32) * ldb + c4;

    const int tx = tid & 15;   // N dir
    const int ty = tid >> 4;   // M dir

    float acc[8][4];
#pragma unroll
    for (int i = 0; i < 8; i++)
#pragma unroll
        for (int j = 0; j < 4; j++) acc[i][j] = 0.f;

    // prologue: load tile 0 into buf 0
    float4 ra0 = *(const float4*)aptr0;
    float4 ra1 = *(const float4*)aptr1;
    float4 rb0 = *(const float4*)bptr0;
    float4 rb1 = *(const float4*)bptr1;
    As[0][c4 + 0][r0] = ra0.x; As[0][c4 + 1][r0] = ra0.y;
    As[0][c4 + 2][r0] = ra0.z; As[0][c4 + 3][r0] = ra0.w;
    As[0][c4 + 0][r0 + 32] = ra1.x; As[0][c4 + 1][r0 + 32] = ra1.y;
    As[0][c4 + 2][r0 + 32] = ra1.z; As[0][c4 + 3][r0 + 32] = ra1.w;
    Bs[0][c4 + 0][r0] = rb0.x; Bs[0][c4 + 1][r0] = rb0.y;
    Bs[0][c4 + 2][r0] = rb0.z; Bs[0][c4 + 3][r0] = rb0.w;
    Bs[0][c4 + 0][r0 + 32] = rb1.x; Bs[0][c4 + 1][r0 + 32] = rb1.y;
    Bs[0][c4 + 2][r0 + 32] = rb1.z; Bs[0][c4 + 3][r0 + 32] = rb1.w;
    __syncthreads();

    const int nK = Kdim >> 4;
    int buf = 0;
    for (int t = 0; t < nK; t++) {
        const bool more = (t + 1 < nK);
        if (more) {
            const int k0 = (t + 1) * BK;
            ra0 = *(const float4*)(aptr0 + k0);
            ra1 = *(const float4*)(aptr1 + k0);
            rb0 = *(const float4*)(bptr0 + k0);
            rb1 = *(const float4*)(bptr1 + k0);
        }
#pragma unroll
        for (int kk = 0; kk < BK; kk++) {
            float4 af0 = *(const float4*)&As[buf][kk][ty * 8];
            float4 af1 = *(const float4*)&As[buf][kk][ty * 8 + 4];
            float4 bf  = *(const float4*)&Bs[buf][kk][tx * 4];
            float a[8] = {af0.x, af0.y, af0.z, af0.w, af1.x, af1.y, af1.z, af1.w};
            float b[4] = {bf.x, bf.y, bf.z, bf.w};
#pragma unroll
            for (int i = 0; i < 8; i++)
#pragma unroll
                for (int j = 0; j < 4; j++)
                    acc[i][j] = fmaf(a[i], b[j], acc[i][j]);
        }
        if (more) {
            const int nb = buf ^ 1;
            As[nb][c4 + 0][r0] = ra0.x; As[nb][c4 + 1][r0] = ra0.y;
            As[nb][c4 + 2][r0] = ra0.z; As[nb][c4 + 3][r0] = ra0.w;
            As[nb][c4 + 0][r0 + 32] = ra1.x; As[nb][c4 + 1][r0 + 32] = ra1.y;
            As[nb][c4 + 2][r0 + 32] = ra1.z; As[nb][c4 + 3][r0 + 32] = ra1.w;
            Bs[nb][c4 + 0][r0] = rb0.x; Bs[nb][c4 + 1][r0] = rb0.y;
            Bs[nb][c4 + 2][r0] = rb0.z; Bs[nb][c4 + 3][r0] = rb0.w;
            Bs[nb][c4 + 0][r0 + 32] = rb1.x; Bs[nb][c4 + 1][r0 + 32] = rb1.y;
            Bs[nb][c4 + 2][r0 + 32] = rb1.z; Bs[nb][c4 + 3][r0 + 32] = rb1.w;
        }
        __syncthreads();
        buf ^= 1;
    }

    // epilogue
    const int cm = by * BM + ty * 8;
    const int cn = bx * BN + tx * 4;
    float4 bc = make_float4(0.f, 0.f, 0.f, 0.f);
    if (MODE == 1) bc = *(const float4*)(bias + cn);
#pragma unroll
    for (int i = 0; i < 8; i++) {
        float4 v;
        v.x = acc[i][0]; v.y = acc[i][1]; v.z = acc[i][2]; v.w = acc[i][3];
        if (MODE == 1) { v.x += bc.x; v.y += bc.y; v.z += bc.z; v.w += bc.w; }
        if (MODE == 3) {
            float rb = bias[cm + i];
            v.x += rb; v.y += rb; v.z += rb; v.w += rb;
        }
        if (MODE == 2) {
            float4 cv = *(const float4*)(Cadd + (size_t)(cm + i) * ldadd + cn);
            v.x += cv.x; v.y += cv.y; v.z += cv.z; v.w += cv.w;
        }
        *(float4*)&C[(size_t)(cm + i) * ldc + cn] = v;
    }
}

// ---------------------------------------------------------------------------
// Concatenate Wv, Wu -> g_W [512,1024]
// ---------------------------------------------------------------------------
__global__ void __launch_bounds__(256)
concat_w(const float* __restrict__ Wv, const float* __restrict__ Wu,
         float* __restrict__ W)
{
    int i = blockIdx.x * 256 + threadIdx.x;   // float4 index, 131072 total
    float4* Wf = (float4*)W;
    const int half = (AA * HH) / 4;           // 65536
    if (i < half) Wf[i] = ((const float4*)Wv)[i];
    else          Wf[i] = ((const float4*)Wu)[i - half];
}

// ---------------------------------------------------------------------------
// Per-mention MIL logit: L[row] = Wa . (tanh(Pv+bv) * sigmoid(Pu+bu)) + ba
// One warp per mention row (2048 rows).
// ---------------------------------------------------------------------------
__global__ void __launch_bounds__(256)
mil_logits(const float* __restrict__ P, const float* __restrict__ bv,
           const float* __restrict__ bu, const float* __restrict__ Wa,
           const float* __restrict__ ba, float* __restrict__ L)
{
    const int w = (blockIdx.x * 256 + threadIdx.x) >> 5;   // 0..2047
    const int lane = threadIdx.x & 31;
    const float* p = P + (size_t)w * (2 * AA);
    float sum = 0.f;
#pragma unroll
    for (int j = 0; j < 8; j++) {
        int a = lane + j * 32;
        float v = tanhf(p[a] + bv[a]);
        float u = 1.f / (1.f + expf(-(p[AA + a] + bu[a])));
        sum += v * u * Wa[a];
    }
#pragma unroll
    for (int o = 16; o; o >>= 1) sum += __shfl_xor_sync(0xffffffffu, sum, o);
    if (lane == 0) L[w] = sum + ba[0];
}

// ---------------------------------------------------------------------------
// Gather per-mention logits, mask, softmax over K=16. One warp per (b,e).
// ---------------------------------------------------------------------------
__global__ void __launch_bounds__(256)
softmax16(const float* __restrict__ L, const int* __restrict__ ent,
          const int* __restrict__ mask, float* __restrict__ attn)
{
    const int w = (blockIdx.x * 256 + threadIdx.x) >> 5;   // be: 0..1023
    const int lane = threadIdx.x & 31;
    const int idx = w * KK + (lane & 15);
    float l = -1e30f;
    if (lane < KK) {
        int m = ent[idx];
        l = mask[idx] ? L[(w >> 7) * MM + m] : -1e25f;
    }
    float mx = l;
#pragma unroll
    for (int o = 8; o; o >>= 1) mx = fmaxf(mx, __shfl_xor_sync(0xffffffffu, mx, o));
    float e = expf(l - mx);
    float s = e;
#pragma unroll
    for (int o = 8; o; o >>= 1) s += __shfl_xor_sync(0xffffffffu, s, o);
    if (lane < KK) attn[idx] = e / s;
}

// ---------------------------------------------------------------------------
// Weighted pooling over K mentions -> entity reprs g_E [BE, H]
// ---------------------------------------------------------------------------
__global__ void __launch_bounds__(256)
pool_kernel(const float* __restrict__ attn, const int* __restrict__ ent,
            const float* __restrict__ mr, float* __restrict__ E)
{
    const int be = blockIdx.x;
    const int b = be >> 7;   // /E
    __shared__ float w[KK];
    __shared__ int rows[KK];
    if (threadIdx.x < KK) {
        w[threadIdx.x] = attn[be * KK + threadIdx.x];
        rows[threadIdx.x] = b * MM + ent[be * KK + threadIdx.x];
    }
    __syncthreads();
    for (int h = threadIdx.x; h < HH; h += 256) {
        float s = 0.f;
#pragma unroll
        for (int k = 0; k < KK; k++)
            s = fmaf(w[k], mr[(size_t)rows[k] * HH + h], s);
        E[(size_t)be * HH + h] = s;
    }
}

// ---------------------------------------------------------------------------
// Transpose relation_memory [R, RMS] -> RMt [RMS, R]
// ---------------------------------------------------------------------------
__global__ void __launch_bounds__(1024)
transpose_rm(const float* __restrict__ RM, float* __restrict__ RMt)
{
    __shared__ float t[32][33];
    const int r0 = blockIdx.y * 32;
    const int m0 = blockIdx.x * 32;
    t[threadIdx.y][threadIdx.x] = RM[(size_t)(r0 + threadIdx.y) * RMS + m0 + threadIdx.x];
    __syncthreads();
    RMt[(size_t)(m0 + threadIdx.y) * RR + r0 + threadIdx.x] = t[threadIdx.x][threadIdx.y];
}

// ---------------------------------------------------------------------------
extern "C" void kernel_launch(void* const* d_in, const int* in_sizes, int n_in,
                              void* d_out, int out_size)
{
    const float* mr   = (const float*)d_in[0];
    const int*   ent  = (const int*)  d_in[1];
    const int*   emask= (const int*)  d_in[2];
    const float* RM   = (const float*)d_in[3];
    const float* Wv   = (const float*)d_in[4];
    const float* bv   = (const float*)d_in[5];
    const float* Wu   = (const float*)d_in[6];
    const float* bu   = (const float*)d_in[7];
    const float* Wa   = (const float*)d_in[8];
    const float* ba   = (const float*)d_in[9];
    const float* Wr   = (const float*)d_in[10];
    const float* br   = (const float*)d_in[11];
    const float* Wo   = (const float*)d_in[12];
    const float* bo   = (const float*)d_in[13];
    float* out = (float*)d_out;

    float *W, *P, *L, *attn, *E, *swT, *RMt, *T, *G;
    cudaGetSymbolAddress((void**)&W,   g_W);
    cudaGetSymbolAddress((void**)&P,   g_P);
    cudaGetSymbolAddress((void**)&L,   g_L);
    cudaGetSymbolAddress((void**)&attn,g_attn);
    cudaGetSymbolAddress((void**)&E,   g_E);
    cudaGetSymbolAddress((void**)&swT, g_swT);
    cudaGetSymbolAddress((void**)&RMt, g_RMt);
    cudaGetSymbolAddress((void**)&T,   g_T);
    cudaGetSymbolAddress((void**)&G,   g_G);

    // --- branch 1: per-mention logits -> attention -> entity reprs ---
    concat_w<<<512, 256>>>(Wv, Wu, W);
    // P[2048,512] = MR[2048,1024] @ W[512,1024]^T
    sgemm_nt<0><<<dim3((2 * AA) / BN, BM_TOT / BM), 128>>>(
        mr, W, nullptr, nullptr, P, HH, HH, 2 * AA, 0, HH);
    mil_logits<<<BM_TOT / 8, 256>>>(P, bv, bu, Wa, ba, L);
    softmax16<<<BE / 8, 256>>>(L, ent, emask, attn);
    pool_kernel<<<BE, 256>>>(attn, ent, mr, E);

    // --- branch 2: E-independent effective weight  G = Wo1^T-ish ---
    // swT[h,r] = Wr[h,:] . RM[r,:] + br[h]   (row bias)
    sgemm_nt<3><<<dim3(RR / BN, HH / BM), 128>>>(
        Wr, RM, br, nullptr, swT, RMS, RMS, RR, 0, RMS);
    transpose_rm<<<dim3(RMS / 32, RR / 32), dim3(32, 32)>>>(RM, RMt);
    // T[h,m] = swT[h,:] . RMt[m,:]   [1024,512]
    sgemm_nt<0><<<dim3(RMS / BN, HH / BM), 128>>>(
        swT, RMt, nullptr, nullptr, T, RR, RR, RMS, 0, RR);
    // G[h',h] = Wo2[h',:] . T[h,:] + Wo1[h',h]
    sgemm_nt<2><<<dim3(HH / BN, HH / BM), 128>>>(
        Wo + HH, T, nullptr, Wo, G, ZW, RMS, HH, ZW, RMS);

    // --- final: out[i,h'] = E[i,:] . G[h',:] + bo[h'] ---
    sgemm_nt<1><<<dim3(HH / BN, BE / BM), 128>>>(
        E, G, bo, nullptr, out, HH, HH, HH, 0, HH);

    (void)in_sizes; (void)n_in; (void)out_size;
}